// round 1
// baseline (speedup 1.0000x reference)
#include <cuda_runtime.h>

#define IN_F   4096
#define OUT_F  11008
#define TOK    16
#define CHUNK  512
#define NCHUNK (IN_F / CHUNK)      // 8
#define WARPS  8
#define THREADS 256
#define RPW    4                   // rows per warp
#define ROWS_PER_CTA (RPW * WARPS) // 32
#define NCTA   (OUT_F / ROWS_PER_CTA) // 344

// Scratch: x transposed to [i][16 tokens], stored as 4 float4 quads per i. 256 KB.
__device__ float4 g_xT[IN_F * 4];

__global__ void transpose_x_kernel(const float* __restrict__ x) {
    int i = blockIdx.x * blockDim.x + threadIdx.x;  // 0..4095
    float v[TOK];
#pragma unroll
    for (int t = 0; t < TOK; t++) v[t] = x[t * IN_F + i];   // coalesced per t
#pragma unroll
    for (int q = 0; q < 4; q++)
        g_xT[i * 4 + q] = make_float4(v[4*q], v[4*q+1], v[4*q+2], v[4*q+3]);
}

typedef unsigned long long u64;

__device__ __forceinline__ u64 pack2(float lo, float hi) {
    u64 r; asm("mov.b64 %0, {%1, %2};" : "=l"(r) : "f"(lo), "f"(hi)); return r;
}
__device__ __forceinline__ void unpack2(u64 v, float& lo, float& hi) {
    asm("mov.b64 {%0, %1}, %2;" : "=f"(lo), "=f"(hi) : "l"(v));
}
// Packed f32x2 FMA: d += a * b  (per-half). PTX-only path to FFMA2 on sm_103a.
__device__ __forceinline__ void ffma2(u64& d, u64 a, u64 b) {
    asm("fma.rn.f32x2 %0, %1, %2, %0;" : "+l"(d) : "l"(a), "l"(b));
}

__global__ void __launch_bounds__(THREADS, 2) q4_gemm_kernel(
    const int*   __restrict__ wq,      // [OUT_F][IN_F] int32 nibbles 0..15
    const float* __restrict__ wscale,  // [OUT_F][IN_F/32]
    const float* __restrict__ bias,    // [OUT_F]
    float*       __restrict__ out)     // [TOK][OUT_F]
{
    // x tile: [quad][slot], slot XOR-swizzled for conflict-free stride-4 reads.
    __shared__ float4 xs[4][CHUNK];    // 32 KB

    const int tid  = threadIdx.x;
    const int warp = tid >> 5;
    const int lane = tid & 31;
    const int row0 = blockIdx.x * ROWS_PER_CTA + warp * RPW;

    u64 acc[RPW][8];                   // 4 rows x 8 token-pairs, fp32x2
#pragma unroll
    for (int r = 0; r < RPW; r++)
#pragma unroll
        for (int k = 0; k < 8; k++) acc[r][k] = 0ull;

    for (int c = 0; c < NCHUNK; c++) {
        const int cbase = c * CHUNK;

        // ---- stage x chunk into smem (coalesced LDG.128, swizzled STS.128) ----
        for (int idx = tid; idx < CHUNK; idx += THREADS) {
            const float4* src = g_xT + (size_t)(cbase + idx) * 4;
            const int slot = idx ^ ((idx >> 3) & 7);
            float4 a0 = src[0], a1 = src[1], a2 = src[2], a3 = src[3];
            xs[0][slot] = a0; xs[1][slot] = a1; xs[2][slot] = a2; xs[3][slot] = a3;
        }
        __syncthreads();

        // ---- main loop: each warp-iteration covers 128 elements (int4/lane) ----
#pragma unroll
        for (int it = 0; it < CHUNK / 128; it++) {
            const int iloc = it * 128 + lane * 4;  // local element index (mult of 4)
            const int gi   = cbase + iloc;         // global element index

            int4 qv[RPW]; float s[RPW], m[RPW];
#pragma unroll
            for (int r = 0; r < RPW; r++) {
                qv[r] = *reinterpret_cast<const int4*>(wq + (row0 + r) * IN_F + gi);
                // gi..gi+3 lie in one 32-block (gi % 4 == 0), one scale per int4
                s[r] = __ldg(&wscale[(row0 + r) * (IN_F / 32) + (gi >> 5)]);
                m[r] = s[r] * -8.0f;               // (q-8)*s = fma(q, s, -8s), exact
            }
#pragma unroll
            for (int j = 0; j < 4; j++) {
                const int ii   = iloc + j;
                const int slot = ii ^ ((ii >> 3) & 7);
                float4 x0 = xs[0][slot], x1 = xs[1][slot],
                       x2 = xs[2][slot], x3 = xs[3][slot];
                u64 xp[8];
                xp[0] = pack2(x0.x, x0.y); xp[1] = pack2(x0.z, x0.w);
                xp[2] = pack2(x1.x, x1.y); xp[3] = pack2(x1.z, x1.w);
                xp[4] = pack2(x2.x, x2.y); xp[5] = pack2(x2.z, x2.w);
                xp[6] = pack2(x3.x, x3.y); xp[7] = pack2(x3.z, x3.w);
#pragma unroll
                for (int r = 0; r < RPW; r++) {
                    const int q = (j == 0) ? qv[r].x : (j == 1) ? qv[r].y
                                : (j == 2) ? qv[r].z : qv[r].w;
                    const float wf = fmaf((float)q, s[r], m[r]);
                    const u64 wp = pack2(wf, wf);
#pragma unroll
                    for (int k = 0; k < 8; k++) ffma2(acc[r][k], wp, xp[k]);
                }
            }
        }
        __syncthreads();
    }

    // ---- warp reduction (butterfly over 32 lanes), lane 0 writes + bias ----
#pragma unroll
    for (int r = 0; r < RPW; r++) {
        const float b = bias[row0 + r];
#pragma unroll
        for (int k = 0; k < 8; k++) {
            float lo, hi; unpack2(acc[r][k], lo, hi);
#pragma unroll
            for (int off = 16; off > 0; off >>= 1) {
                lo += __shfl_xor_sync(0xffffffffu, lo, off);
                hi += __shfl_xor_sync(0xffffffffu, hi, off);
            }
            if (lane == 0) {
                out[(2 * k)     * OUT_F + row0 + r] = lo + b;
                out[(2 * k + 1) * OUT_F + row0 + r] = hi + b;
            }
        }
    }
}

extern "C" void kernel_launch(void* const* d_in, const int* in_sizes, int n_in,
                              void* d_out, int out_size) {
    const float* x      = (const float*)d_in[0];  // [16, 4096]
    const int*   wq     = (const int*)  d_in[1];  // [11008, 4096]
    const float* wscale = (const float*)d_in[2];  // [11008, 128]
    const float* bias   = (const float*)d_in[3];  // [11008]
    float* out = (float*)d_out;                   // [16, 11008]

    transpose_x_kernel<<<IN_F / 256, 256>>>(x);
    q4_gemm_kernel<<<NCTA, THREADS>>>(wq, wscale, bias, out);
}